// round 1
// baseline (speedup 1.0000x reference)
#include <cuda_runtime.h>
#include <math.h>

#define BATCH 32
#define CIN   256
#define OHW   28
#define HW    784          // 28*28
#define IH    56
#define IHW   3136         // 56*56

// ---------------- scratch (static device allocations; no cudaMalloc) ----------------
__device__ float g_f1r [BATCH * CIN * HW];          // resized feature1  [b][c][q]
__device__ float g_f2r [BATCH * CIN * HW];          // resized feature2  [b][c][q]
__device__ float g_mpool[BATCH * HW];               // maxpooled mask    [b][q]
__device__ float g_scale[BATCH * HW];               // mask/||corr||     [b][q]
__device__ float g_corr [BATCH * HW * HW];          // relu(corr)        [b][p][q]
__device__ float g_pool [BATCH * HW * HW];          // maxpool3(corr*s)  [b][p][q]
__device__ float g_y2a  [BATCH * 192 * HW];
__device__ float g_y3a  [BATCH *  32 * HW];
__device__ float g_y    [BATCH * 512 * HW];         // concat buffer
__device__ float g_mean [512];
__device__ float g_inv  [512];

// ---------------- bilinear resize 56->28, align_corners=True ----------------
__global__ void resize_k(const float* __restrict__ f1, const float* __restrict__ f2) {
    int idx = blockIdx.x * blockDim.x + threadIdx.x;
    const int total = BATCH * CIN * HW;
    if (idx >= 2 * total) return;
    const float* src = (idx < total) ? f1 : f2;
    float* dst       = (idx < total) ? g_f1r : g_f2r;
    int i  = (idx < total) ? idx : idx - total;
    int q  = i % HW;
    int bc = i / HW;
    int oy = q / OHW, ox = q % OHW;
    const float step = 55.0f / 27.0f;
    float fy = oy * step, fx = ox * step;
    int y0 = (int)floorf(fy); if (y0 > IH - 1) y0 = IH - 1;
    int x0 = (int)floorf(fx); if (x0 > IH - 1) x0 = IH - 1;
    int y1 = min(y0 + 1, IH - 1);
    int x1 = min(x0 + 1, IH - 1);
    float wy = fy - (float)y0;
    float wx = fx - (float)x0;
    const float* p = src + (size_t)bc * IHW;
    float v00 = p[y0 * IH + x0], v01 = p[y0 * IH + x1];
    float v10 = p[y1 * IH + x0], v11 = p[y1 * IH + x1];
    float r0 = v00 * (1.0f - wy) + v10 * wy;   // y-interp first (matches ref order)
    float r1 = v01 * (1.0f - wy) + v11 * wy;
    dst[i] = r0 * (1.0f - wx) + r1 * wx;
}

// ---------------- mask maxpool 2x2 s2 ----------------
__global__ void mpool_k(const float* __restrict__ mask) {
    int idx = blockIdx.x * blockDim.x + threadIdx.x;
    if (idx >= BATCH * HW) return;
    int b = idx / HW, q = idx % HW;
    int y = q / OHW, x = q % OHW;
    const float* p = mask + (size_t)b * IHW;
    float m0 = p[(2*y)   * IH + 2*x], m1 = p[(2*y)   * IH + 2*x + 1];
    float m2 = p[(2*y+1) * IH + 2*x], m3 = p[(2*y+1) * IH + 2*x + 1];
    g_mpool[idx] = fmaxf(fmaxf(m0, m1), fmaxf(m2, m3));
}

// ---------------- generic tiled GEMM with fused epilogue ----------------
// C[b][m][n] = relu( scale?[b][n] * (sum_k A[b][m][k or k][m] * B[b][k][n]) + bias?[m] )
// A addressing: Ab[k*sAk + m*sAm]. B: plain [k][n] (stride N) or conv im2col decode.
template <int CONVK>
__global__ void gemm_k(const float* __restrict__ A, const float* __restrict__ Bm,
                       float* __restrict__ C,
                       int M, int N, int K,
                       long aB, long bB, long cB,
                       int sAk, int sAm,
                       int pad,
                       const float* __restrict__ scale,
                       const float* __restrict__ bias,
                       int cStride)
{
    const int b = blockIdx.z;
    const float* Ab = A  + (size_t)b * aB;
    const float* Bb = Bm + (size_t)b * bB;
    float*       Cb = C  + (size_t)b * cB;
    const int m0 = blockIdx.y * 64;
    const int n0 = blockIdx.x * 64;

    __shared__ float As[16][68];
    __shared__ float Bs[16][68];

    const int tid = threadIdx.x;
    const int tx = tid & 15;
    const int ty = tid >> 4;

    float acc[4][4];
#pragma unroll
    for (int i = 0; i < 4; i++)
#pragma unroll
        for (int j = 0; j < 4; j++) acc[i][j] = 0.0f;

    for (int k0 = 0; k0 < K; k0 += 16) {
        // ---- load A tile ----
        if (sAk == 1) {       // weight layout [m][k], k contiguous
#pragma unroll
            for (int l = 0; l < 4; l++) {
                int e = tid + l * 256;
                int k = e & 15, m = e >> 4;
                float v = 0.0f;
                if (m0 + m < M) v = Ab[(size_t)(m0 + m) * sAm + (k0 + k)];
                As[k][m] = v;
            }
        } else {              // [k][m], m contiguous
#pragma unroll
            for (int l = 0; l < 4; l++) {
                int e = tid + l * 256;
                int k = e >> 6, m = e & 63;
                float v = 0.0f;
                if (m0 + m < M) v = Ab[(size_t)(k0 + k) * sAk + (m0 + m)];
                As[k][m] = v;
            }
        }
        // ---- load B tile ----
        if (CONVK == 0) {
#pragma unroll
            for (int l = 0; l < 4; l++) {
                int e = tid + l * 256;
                int k = e >> 6, n = e & 63;
                float v = 0.0f;
                if (n0 + n < N) v = Bb[(size_t)(k0 + k) * N + (n0 + n)];
                Bs[k][n] = v;
            }
        } else {
            const int kk2 = CONVK * CONVK;
#pragma unroll
            for (int l = 0; l < 4; l++) {
                int e = tid + l * 256;
                int k = e >> 6, n = e & 63;
                float v = 0.0f;
                int gn = n0 + n;
                if (gn < N) {
                    int gk = k0 + k;
                    int c  = gk / kk2, r = gk % kk2;
                    int ky = r / CONVK, kx = r % CONVK;
                    int y  = gn / OHW + ky - pad;
                    int x  = gn % OHW + kx - pad;
                    if (y >= 0 && y < OHW && x >= 0 && x < OHW)
                        v = Bb[c * HW + y * OHW + x];
                }
                Bs[k][n] = v;
            }
        }
        __syncthreads();

#pragma unroll
        for (int kk = 0; kk < 16; kk++) {
            float4 av = *(const float4*)&As[kk][ty * 4];
            float4 bv = *(const float4*)&Bs[kk][tx * 4];
            float a0[4] = {av.x, av.y, av.z, av.w};
            float b0[4] = {bv.x, bv.y, bv.z, bv.w};
#pragma unroll
            for (int i = 0; i < 4; i++)
#pragma unroll
                for (int j = 0; j < 4; j++)
                    acc[i][j] += a0[i] * b0[j];
        }
        __syncthreads();
    }

    // ---- epilogue ----
#pragma unroll
    for (int i = 0; i < 4; i++) {
        int m = m0 + ty * 4 + i;
        if (m >= M) continue;
        float bi = bias ? bias[m] : 0.0f;
#pragma unroll
        for (int j = 0; j < 4; j++) {
            int n = n0 + tx * 4 + j;
            if (n >= N) continue;
            float v = acc[i][j];
            if (scale) v *= scale[(size_t)b * HW + n];
            v += bi;
            if (v < 0.0f) v = 0.0f;
            Cb[(size_t)m * cStride + n] = v;
        }
    }
}

// ---------------- per-column L2 norm of corr -> scale = mask / norm ----------------
__global__ void norm_k() {
    int idx = blockIdx.x * blockDim.x + threadIdx.x;
    if (idx >= BATCH * HW) return;
    int b = idx / HW, q = idx % HW;
    const float* base = g_corr + (size_t)b * HW * HW + q;
    float s0 = 0.f, s1 = 0.f, s2 = 0.f, s3 = 0.f;
    int p = 0;
    for (; p + 4 <= HW; p += 4) {
        float v0 = base[(p    ) * HW];
        float v1 = base[(p + 1) * HW];
        float v2 = base[(p + 2) * HW];
        float v3 = base[(p + 3) * HW];
        s0 += v0 * v0; s1 += v1 * v1; s2 += v2 * v2; s3 += v3 * v3;
    }
    float s = (s0 + s1) + (s2 + s3);
    g_scale[idx] = g_mpool[idx] / sqrtf(s);
}

// ---------------- maxpool 3x3 s1 pad1 over scaled corr ----------------
__global__ void pool_k() {
    int idx = blockIdx.x * blockDim.x + threadIdx.x;
    if (idx >= BATCH * HW * HW) return;
    int q  = idx % HW;
    int bp = idx / HW;
    int b  = bp / HW;
    int y  = q / OHW, x = q % OHW;
    const float* row = g_corr + (size_t)bp * HW;
    const float* sc  = g_scale + (size_t)b * HW;
    float mx = -INFINITY;
#pragma unroll
    for (int dy = -1; dy <= 1; dy++) {
        int iy = y + dy;
        if (iy < 0 || iy >= OHW) continue;
#pragma unroll
        for (int dx = -1; dx <= 1; dx++) {
            int ix = x + dx;
            if (ix < 0 || ix >= OHW) continue;
            int qq = iy * OHW + ix;
            float v = row[qq] * sc[qq];
            mx = fmaxf(mx, v);
        }
    }
    g_pool[idx] = mx;
}

// ---------------- batchnorm stats (training-mode, biased var) ----------------
__global__ void bnstat_k() {
    const int ch  = blockIdx.x;
    const int tid = threadIdx.x;
    const int NEL = BATCH * HW;
    double s = 0.0, ss = 0.0;
    for (int i = tid; i < NEL; i += blockDim.x) {
        int b = i / HW, q = i % HW;
        float v = g_y[(size_t)b * 512 * HW + (size_t)ch * HW + q];
        s  += (double)v;
        ss += (double)v * (double)v;
    }
    __shared__ double sh[256];
    __shared__ double sh2[256];
    sh[tid] = s; sh2[tid] = ss;
    __syncthreads();
    for (int st = 128; st > 0; st >>= 1) {
        if (tid < st) { sh[tid] += sh[tid + st]; sh2[tid] += sh2[tid + st]; }
        __syncthreads();
    }
    if (tid == 0) {
        double mean = sh[0] / NEL;
        double var  = sh2[0] / NEL - mean * mean;
        g_mean[ch] = (float)mean;
        g_inv[ch]  = (float)(1.0 / sqrt(var + 1e-5));
    }
}

__global__ void bnapply_k(const float* __restrict__ gamma,
                          const float* __restrict__ beta,
                          float* __restrict__ out) {
    int idx = blockIdx.x * blockDim.x + threadIdx.x;
    if (idx >= BATCH * 512 * HW) return;
    int ch = (idx / HW) % 512;
    out[idx] = gamma[ch] * (g_y[idx] - g_mean[ch]) * g_inv[ch] + beta[ch];
}

// ---------------- launch ----------------
static float* sym_addr(const void* symbol) {
    void* p = nullptr;
    cudaGetSymbolAddress(&p, symbol);
    return (float*)p;
}

extern "C" void kernel_launch(void* const* d_in, const int* in_sizes, int n_in,
                              void* d_out, int out_size) {
    const float* feature1 = (const float*)d_in[0];
    const float* feature2 = (const float*)d_in[1];
    const float* mask     = (const float*)d_in[2];
    const float* W1  = (const float*)d_in[3];
    const float* b1  = (const float*)d_in[4];
    const float* W2a = (const float*)d_in[5];
    const float* b2a = (const float*)d_in[6];
    const float* W2b = (const float*)d_in[7];
    const float* b2b = (const float*)d_in[8];
    const float* W3a = (const float*)d_in[9];
    const float* b3a = (const float*)d_in[10];
    const float* W3b = (const float*)d_in[11];
    const float* b3b = (const float*)d_in[12];
    const float* W4  = (const float*)d_in[13];
    const float* b4  = (const float*)d_in[14];
    const float* gamma = (const float*)d_in[15];
    const float* beta  = (const float*)d_in[16];
    float* out = (float*)d_out;

    float* f1r  = sym_addr(g_f1r);
    float* f2r  = sym_addr(g_f2r);
    float* corr = sym_addr(g_corr);
    float* pool = sym_addr(g_pool);
    float* scal = sym_addr(g_scale);
    float* y2a  = sym_addr(g_y2a);
    float* y3a  = sym_addr(g_y3a);
    float* ybuf = sym_addr(g_y);

    // 1) resize both features
    {
        int total = 2 * BATCH * CIN * HW;
        resize_k<<<(total + 255) / 256, 256>>>(feature1, feature2);
    }
    // 2) mask maxpool
    mpool_k<<<(BATCH * HW + 255) / 256, 256>>>(mask);

    // 3) correlation GEMM: corr[b][p][q] = relu(sum_c f1r[b][c][p] * f2r[b][c][q])
    {
        dim3 grid(13, 13, BATCH);
        gemm_k<0><<<grid, 256>>>(f1r, f2r, corr,
                                 HW, HW, CIN,
                                 (long)CIN * HW, (long)CIN * HW, (long)HW * HW,
                                 HW, 1, 0, nullptr, nullptr, HW);
    }
    // 4) column L2 norm -> scale
    norm_k<<<(BATCH * HW + 255) / 256, 256>>>();

    // 5) 3x3 maxpool over scaled corr
    {
        long total = (long)BATCH * HW * HW;
        pool_k<<<(int)((total + 255) / 256), 256>>>();
    }

    // 6-9) 1x1 conv branches (scale folded into epilogue for branches on corr)
    {
        dim3 g1(13, 2, BATCH);   // W1: 128 out -> y channels [0,128)
        gemm_k<0><<<g1, 256>>>(W1, corr, ybuf,
                               128, HW, HW,
                               0L, (long)HW * HW, (long)512 * HW,
                               1, HW, 0, scal, b1, HW);
        dim3 g2(13, 3, BATCH);   // W2a: 192 out -> y2a
        gemm_k<0><<<g2, 256>>>(W2a, corr, y2a,
                               192, HW, HW,
                               0L, (long)HW * HW, (long)192 * HW,
                               1, HW, 0, scal, b2a, HW);
        dim3 g3(13, 1, BATCH);   // W3a: 32 out -> y3a
        gemm_k<0><<<g3, 256>>>(W3a, corr, y3a,
                               32, HW, HW,
                               0L, (long)HW * HW, (long)32 * HW,
                               1, HW, 0, scal, b3a, HW);
        dim3 g4(13, 1, BATCH);   // W4 on pooled (already scaled) -> y channels [448,512)
        gemm_k<0><<<g4, 256>>>(W4, pool, ybuf + (size_t)448 * HW,
                               64, HW, HW,
                               0L, (long)HW * HW, (long)512 * HW,
                               1, HW, 0, nullptr, b4, HW);
    }
    // 10) 3x3 conv 192->256 (implicit GEMM) -> y channels [128,384)
    {
        dim3 g(13, 4, BATCH);
        gemm_k<3><<<g, 256>>>(W2b, y2a, ybuf + (size_t)128 * HW,
                              256, HW, 192 * 9,
                              0L, (long)192 * HW, (long)512 * HW,
                              1, 192 * 9, 1, nullptr, b2b, HW);
    }
    // 11) 5x5 conv 32->64 (implicit GEMM) -> y channels [384,448)
    {
        dim3 g(13, 1, BATCH);
        gemm_k<5><<<g, 256>>>(W3b, y3a, ybuf + (size_t)384 * HW,
                              64, HW, 32 * 25,
                              0L, (long)32 * HW, (long)512 * HW,
                              1, 32 * 25, 2, nullptr, b3b, HW);
    }
    // 12) batchnorm stats + apply
    bnstat_k<<<512, 256>>>();
    {
        int total = BATCH * 512 * HW;
        bnapply_k<<<(total + 255) / 256, 256>>>(gamma, beta, out);
    }
}